// round 13
// baseline (speedup 1.0000x reference)
#include <cuda_runtime.h>
#include <cuda_fp16.h>
#include <cstdint>

#define N_NODES 100000
#define N_EDGES 3200000
#define F_IN 64
#define HID 20
#define ROWH 32                             // halves per padded row (64B)
#define N_GRAPHS 128
#define N_CLASSES 10
#define EPS_NORM 1e-12f
#define SCAN_B ((N_NODES + 1023) / 1024)    // 98

// ---------------- scratch (device globals) ---------------------------------
__device__ __align__(128) __half g_bufA[N_NODES * ROWH];  // fp16 rows, 64B stride
__device__ __align__(128) __half g_bufB[N_NODES * ROWH];
__device__ __align__(16) int g_edge_raw[2 * N_EDGES];     // int2 (s,w) or int (s)
__device__ int g_deg[N_NODES];
__device__ int g_rowptr[N_NODES + 1];
__device__ int g_cursor[N_NODES];
__device__ int g_bsum[128];
__device__ int g_boff[128];
__device__ float g_pmax[N_GRAPHS * HID];
__device__ float g_psum[N_GRAPHS * HID];
__device__ float g_cnt[N_GRAPHS];
__device__ int   g_is64;
__device__ int   g_wuni;                                  // 1 if all weights == 1.0f

// ---------------- init: dtype probe + zero deg/pool + row padding -----------
__global__ void k_init(const void* __restrict__ ei) {
    int i = blockIdx.x * blockDim.x + threadIdx.x;
    if (i == 0) {
        const long long* p = (const long long*)ei;
        bool ok = true;
        #pragma unroll
        for (int q = 0; q < 16; q++) {
            long long v = p[q];
            if (v < 0 || v >= (long long)N_NODES) ok = false;
        }
        g_is64 = ok ? 1 : 0;
        g_wuni = 1;
    }
    if (i < N_NODES) {
        g_deg[i] = 0;
        // zero padding halves [20,32) of each row in both buffers
        char* ra = (char*)g_bufA + (size_t)i * 64;
        char* rb = (char*)g_bufB + (size_t)i * 64;
        *(uint2*)(ra + 40) = make_uint2(0u, 0u);
        *(uint4*)(ra + 48) = make_uint4(0u, 0u, 0u, 0u);
        *(uint2*)(rb + 40) = make_uint2(0u, 0u);
        *(uint4*)(rb + 48) = make_uint4(0u, 0u, 0u, 0u);
    }
    if (i < N_GRAPHS * HID) { g_pmax[i] = 0.0f; g_psum[i] = 0.0f; }
    if (i < N_GRAPHS) g_cnt[i] = 0.0f;
}

// ---------------- CSR build -------------------------------------------------
__global__ void k_hist(const void* __restrict__ ei, const float* __restrict__ w) {
    int e = blockIdx.x * blockDim.x + threadIdx.x;
    if (e >= N_EDGES) return;
    int d;
    if (g_is64) d = (int)((const long long*)ei)[N_EDGES + e];
    else        d = ((const int*)ei)[N_EDGES + e];
    atomicAdd(&g_deg[d], 1);
    if (w[e] != 1.0f) g_wuni = 0;   // benign race: all writers store 0
}

__global__ void k_scan1() {
    __shared__ int s[1024];
    int t = threadIdx.x;
    int i = blockIdx.x * 1024 + t;
    s[t] = (i < N_NODES) ? g_deg[i] : 0;
    __syncthreads();
    #pragma unroll
    for (int off = 512; off > 0; off >>= 1) {
        if (t < off) s[t] += s[t + off];
        __syncthreads();
    }
    if (t == 0) g_bsum[blockIdx.x] = s[0];
}

__global__ void k_scan2() {
    if (threadIdx.x == 0) {
        int run = 0;
        for (int i = 0; i < SCAN_B; i++) {
            g_boff[i] = run;
            run += g_bsum[i];
        }
        g_rowptr[N_NODES] = run;
    }
}

__global__ void k_scan3() {
    __shared__ int s[1024];
    int t = threadIdx.x;
    int i = blockIdx.x * 1024 + t;
    int v = (i < N_NODES) ? g_deg[i] : 0;
    s[t] = v;
    __syncthreads();
    #pragma unroll
    for (int off = 1; off < 1024; off <<= 1) {
        int u = (t >= off) ? s[t - off] : 0;
        __syncthreads();
        s[t] += u;
        __syncthreads();
    }
    if (i < N_NODES) {
        int ex = s[t] - v + g_boff[blockIdx.x];
        g_rowptr[i] = ex;
        g_cursor[i] = ex;
    }
}

__global__ void k_fill(const void* __restrict__ ei, const float* __restrict__ w) {
    int e = blockIdx.x * blockDim.x + threadIdx.x;
    if (e >= N_EDGES) return;
    int s, d;
    if (g_is64) {
        const long long* p = (const long long*)ei;
        s = (int)p[e]; d = (int)p[N_EDGES + e];
    } else {
        const int* p = (const int*)ei;
        s = p[e]; d = p[N_EDGES + e];
    }
    int pos = atomicAdd(&g_cursor[d], 1);
    if (g_wuni) {
        g_edge_raw[pos] = s;                          // src only, 4B
    } else {
        ((int2*)g_edge_raw)[pos] = make_int2(s, __float_as_int(w[e]));
    }
}

// ---------------- layer-1 input GEMM: bufA = fp16(x @ W1a) ------------------
__global__ __launch_bounds__(256) void k_gemm_in(const float* __restrict__ x,
                                                 const float* __restrict__ W) {
    __shared__ float sW[F_IN * HID];   // 5.1 KB
    int tid = threadIdx.x;
    for (int i = tid; i < F_IN * HID; i += 256) sW[i] = W[i];
    __syncthreads();
    int n = blockIdx.x * 256 + tid;
    if (n >= N_NODES) return;

    const float4* xr = (const float4*)(x + (size_t)n * F_IN);

    float acc[HID];
    #pragma unroll
    for (int j = 0; j < HID; j++) acc[j] = 0.0f;

    #pragma unroll
    for (int c = 0; c < 4; c++) {
        float4 xv[4];
        #pragma unroll
        for (int q = 0; q < 4; q++) xv[q] = __ldg(xr + c * 4 + q);
        const float* xs = (const float*)xv;
        #pragma unroll
        for (int kk = 0; kk < 16; kk++) {
            int k = c * 16 + kk;
            float xk = xs[kk];
            const float4* wr = (const float4*)&sW[k * HID];
            #pragma unroll
            for (int q = 0; q < 5; q++) {
                float4 wv = wr[q];
                acc[4 * q + 0] += xk * wv.x;
                acc[4 * q + 1] += xk * wv.y;
                acc[4 * q + 2] += xk * wv.z;
                acc[4 * q + 3] += xk * wv.w;
            }
        }
    }
    // full 64B row store (padding halves zeroed)
    unsigned hp[16];
    #pragma unroll
    for (int q = 0; q < 10; q++) {
        __half2 h = __floats2half2_rn(acc[2 * q], acc[2 * q + 1]);
        hp[q] = *(unsigned*)&h;
    }
    #pragma unroll
    for (int q = 10; q < 16; q++) hp[q] = 0u;
    uint4* op = (uint4*)(g_bufA + (size_t)n * ROWH);
    op[0] = make_uint4(hp[0], hp[1], hp[2], hp[3]);
    op[1] = make_uint4(hp[4], hp[5], hp[6], hp[7]);
    op[2] = make_uint4(hp[8], hp[9], hp[10], hp[11]);
    op[3] = make_uint4(hp[12], hp[13], hp[14], hp[15]);
}

// ---------------- fused aggregation + warp MLP ------------------------------
// Gather: 10 groups x 3 lanes; 48B of the 64B-aligned row -> 1 wavefront/edge.
// Epilogue: lane j owns feature j; MLP via shfl; mode 2 fuses pooling.
// mode: 0 bufA->bufB, 1 bufB->bufA, 2 bufA->pooled atomics.
#define AW 8
__global__ __launch_bounds__(AW * 32) void k_agg(
        const float* __restrict__ ba, const float* __restrict__ Wb,
        const float* __restrict__ bb, const float* __restrict__ Wn,
        const void* __restrict__ batch_v, int mode) {
    __shared__ float sWb[HID * HID], sWn[HID * HID], sba[HID], sbb[HID];
    __shared__ float red[AW][32][9];   // [warp][lane][8 feats + pad]
    int tid = threadIdx.x;
    for (int i = tid; i < HID * HID; i += AW * 32) {
        sWb[i] = Wb[i];
        sWn[i] = Wn ? Wn[i] : 0.0f;
    }
    if (tid < HID) { sba[tid] = ba[tid]; sbb[tid] = bb[tid]; }
    __syncthreads();

    int wid = tid >> 5, lane = tid & 31;
    int n = blockIdx.x * AW + wid;
    if (n >= N_NODES) return;

    const char* in = (const char*)((mode == 1) ? g_bufB : g_bufA);
    __half* outp = (mode == 0) ? g_bufB : g_bufA;
    bool uni = (g_wuni != 0);
    int rs = __ldg(&g_rowptr[n]);
    int re = __ldg(&g_rowptr[n + 1]);

    int grp  = lane / 3;           // 0..9 valid; 10 for lanes 30,31
    int role = lane - grp * 3;     // 0..2
    bool active = grp < 10;

    float acc[8];
    #pragma unroll
    for (int j = 0; j < 8; j++) acc[j] = 0.0f;

    if (active) {
        if (uni) {
            const int* ep = g_edge_raw;
            for (int e = rs + grp; e < re; e += 10) {
                int s = __ldg(ep + e);                       // broadcast within group
                uint4 v = __ldg((const uint4*)(in + (size_t)s * 64) + role);
                unsigned hp[4] = {v.x, v.y, v.z, v.w};
                #pragma unroll
                for (int q = 0; q < 4; q++) {
                    float2 f = __half22float2(*(__half2*)&hp[q]);
                    acc[2 * q + 0] += f.x;
                    acc[2 * q + 1] += f.y;
                }
            }
        } else {
            const int2* ep = (const int2*)g_edge_raw;
            for (int e = rs + grp; e < re; e += 10) {
                int2 p = __ldg(ep + e);
                float w = __int_as_float(p.y);
                uint4 v = __ldg((const uint4*)(in + (size_t)p.x * 64) + role);
                unsigned hp[4] = {v.x, v.y, v.z, v.w};
                #pragma unroll
                for (int q = 0; q < 4; q++) {
                    float2 f = __half22float2(*(__half2*)&hp[q]);
                    acc[2 * q + 0] += f.x * w;
                    acc[2 * q + 1] += f.y * w;
                }
            }
        }
    }

    // transpose-reduce: feature f = 8*role + j lives in lanes {3g + role}
    float (*rp)[9] = red[wid];
    #pragma unroll
    for (int j = 0; j < 8; j++) rp[lane][j] = acc[j];
    __syncwarp();

    float s = 0.0f;
    if (lane < HID) {
        int r = lane >> 3, j = lane & 7;
        #pragma unroll
        for (int g = 0; g < 10; g++) s += rp[3 * g + r][j];
    }

    // ---- warp MLP: lane j owns feature j (lanes >= HID carry zeros) ----
    const unsigned m = 0xffffffffu;
    int lj = (lane < HID) ? lane : 0;            // safe smem index
    float zj = (lane < HID) ? fmaxf(s + sba[lane], 0.0f) : 0.0f;

    float z2j = 0.0f;
    #pragma unroll
    for (int k = 0; k < HID; k++) {
        float zk = __shfl_sync(m, zj, k);
        z2j += zk * sWb[k * HID + lj];
    }
    z2j = (lane < HID) ? fmaxf(z2j + sbb[lane], 0.0f) : 0.0f;

    float ss = z2j * z2j;
    #pragma unroll
    for (int off = 16; off > 0; off >>= 1) ss += __shfl_xor_sync(m, ss, off);
    float inv = 1.0f / fmaxf(sqrtf(ss), EPS_NORM);
    float hj = fmaxf(z2j * inv, 0.0f);           // zero for lanes >= HID

    if (mode != 2) {
        float oj = 0.0f;
        #pragma unroll
        for (int k = 0; k < HID; k++) {
            float hk = __shfl_sync(m, hj, k);
            oj += hk * sWn[k * HID + lj];
        }
        if (lane < HID)
            outp[(size_t)n * ROWH + lane] = __float2half(oj);  // same 64B line
        return;
    }

    // ---- fused pooling (mode 2): one node per warp ----
    int g;
    if (g_is64) g = (int)((const long long*)batch_v)[n];
    else        g = ((const int*)batch_v)[n];
    if (lane < HID) {
        atomicAdd(&g_psum[g * HID + lane], hj);
        atomicMax((int*)&g_pmax[g * HID + lane], __float_as_int(hj));  // h >= 0
    }
    if (lane == 0) atomicAdd(&g_cnt[g], 1.0f);
}

__global__ void k_final(const float* __restrict__ Wlin, const float* __restrict__ blin,
                        float* __restrict__ out) {
    int idx = blockIdx.x * blockDim.x + threadIdx.x;
    if (idx >= N_GRAPHS * N_CLASSES) return;
    int gph = idx / N_CLASSES, c = idx % N_CLASSES;
    float cnt = g_cnt[gph];
    float icnt = 1.0f / fmaxf(cnt, 1.0f);
    float acc = __ldg(blin + c);
    #pragma unroll
    for (int k = 0; k < HID; k++) {
        float mx = (cnt > 0.0f) ? g_pmax[gph * HID + k] : 0.0f;
        float mean = g_psum[gph * HID + k] * icnt;
        acc += mx * __ldg(Wlin + k * N_CLASSES + c)
             + mean * __ldg(Wlin + (HID + k) * N_CLASSES + c);
    }
    out[idx] = acc;
}

// ---------------- launch ----------------------------------------------------
extern "C" void kernel_launch(void* const* d_in, const int* in_sizes, int n_in,
                              void* d_out, int out_size) {
    const float* x    = (const float*)d_in[0];
    const void*  ei   = d_in[1];
    const void*  batch= d_in[2];
    const float* ew   = (const float*)d_in[3];
    const float* W1a  = (const float*)d_in[4];
    const float* b1a  = (const float*)d_in[5];
    const float* W1b  = (const float*)d_in[6];
    const float* b1b  = (const float*)d_in[7];
    const float* W2a  = (const float*)d_in[8];
    const float* b2a  = (const float*)d_in[9];
    const float* W2b  = (const float*)d_in[10];
    const float* b2b  = (const float*)d_in[11];
    const float* W3a  = (const float*)d_in[12];
    const float* b3a  = (const float*)d_in[13];
    const float* W3b  = (const float*)d_in[14];
    const float* b3b  = (const float*)d_in[15];
    const float* Wlin = (const float*)d_in[16];
    const float* blin = (const float*)d_in[17];
    float* out = (float*)d_out;

    const int eg = (N_EDGES + 255) / 256;
    const int ng = (N_NODES + 255) / 256;
    const int ag = (N_NODES + AW - 1) / AW;
    const int gg = (N_NODES + 255) / 256;

    k_init<<<ng, 256>>>(ei);
    k_hist<<<eg, 256>>>(ei, ew);
    k_gemm_in<<<gg, 256>>>(x, W1a);
    k_scan1<<<SCAN_B, 1024>>>();
    k_scan2<<<1, 32>>>();
    k_scan3<<<SCAN_B, 1024>>>();
    k_fill<<<eg, 256>>>(ei, ew);

    // three fused layers: gather (1 wf/edge) + warp MLP; layer 3 fuses pooling
    k_agg<<<ag, AW * 32>>>(b1a, W1b, b1b, W2a, nullptr, 0);
    k_agg<<<ag, AW * 32>>>(b2a, W2b, b2b, W3a, nullptr, 1);
    k_agg<<<ag, AW * 32>>>(b3a, W3b, b3b, nullptr, batch, 2);

    k_final<<<2, 640>>>(Wlin, blin, out);
}

// round 14
// speedup vs baseline: 1.4444x; 1.4444x over previous
#include <cuda_runtime.h>
#include <cuda_fp16.h>
#include <cstdint>

#define N_NODES 100000
#define N_EDGES 3200000
#define F_IN 64
#define HID 20
#define ROWH 32                             // halves per padded row (64B)
#define N_GRAPHS 128
#define N_CLASSES 10
#define EPS_NORM 1e-12f
#define SCAN_B ((N_NODES + 1023) / 1024)    // 98

// ---------------- scratch (device globals) ---------------------------------
__device__ __align__(128) __half g_bufA[N_NODES * ROWH];  // fp16 rows, 64B stride
__device__ __align__(128) __half g_bufB[N_NODES * ROWH];
__device__ __align__(16) float g_agg[N_NODES * HID];
__device__ __align__(16) int g_edge_raw[2 * N_EDGES];     // int2 (s,w) or int (s)
__device__ int g_deg[N_NODES];
__device__ int g_rowptr[N_NODES + 1];
__device__ int g_cursor[N_NODES];
__device__ int g_bsum[128];
__device__ int g_boff[128];
__device__ float g_pmax[N_GRAPHS * HID];
__device__ float g_psum[N_GRAPHS * HID];
__device__ float g_cnt[N_GRAPHS];
__device__ int   g_is64;
__device__ int   g_wuni;                                  // 1 if all weights == 1.0f

// ---------------- init: dtype probe + zero deg/pool -------------------------
__global__ void k_init(const void* __restrict__ ei) {
    int i = blockIdx.x * blockDim.x + threadIdx.x;
    if (i == 0) {
        const long long* p = (const long long*)ei;
        bool ok = true;
        #pragma unroll
        for (int q = 0; q < 16; q++) {
            long long v = p[q];
            if (v < 0 || v >= (long long)N_NODES) ok = false;
        }
        g_is64 = ok ? 1 : 0;
        g_wuni = 1;
    }
    if (i < N_NODES) g_deg[i] = 0;
    if (i < N_GRAPHS * HID) { g_pmax[i] = 0.0f; g_psum[i] = 0.0f; }
    if (i < N_GRAPHS) g_cnt[i] = 0.0f;
}

// ---------------- CSR build -------------------------------------------------
__global__ void k_hist(const void* __restrict__ ei, const float* __restrict__ w) {
    int e = blockIdx.x * blockDim.x + threadIdx.x;
    if (e >= N_EDGES) return;
    int d;
    if (g_is64) d = (int)((const long long*)ei)[N_EDGES + e];
    else        d = ((const int*)ei)[N_EDGES + e];
    atomicAdd(&g_deg[d], 1);
    if (w[e] != 1.0f) g_wuni = 0;   // benign race: all writers store 0
}

__global__ void k_scan1() {
    __shared__ int s[1024];
    int t = threadIdx.x;
    int i = blockIdx.x * 1024 + t;
    s[t] = (i < N_NODES) ? g_deg[i] : 0;
    __syncthreads();
    #pragma unroll
    for (int off = 512; off > 0; off >>= 1) {
        if (t < off) s[t] += s[t + off];
        __syncthreads();
    }
    if (t == 0) g_bsum[blockIdx.x] = s[0];
}

__global__ void k_scan2() {
    if (threadIdx.x == 0) {
        int run = 0;
        for (int i = 0; i < SCAN_B; i++) {
            g_boff[i] = run;
            run += g_bsum[i];
        }
        g_rowptr[N_NODES] = run;
    }
}

__global__ void k_scan3() {
    __shared__ int s[1024];
    int t = threadIdx.x;
    int i = blockIdx.x * 1024 + t;
    int v = (i < N_NODES) ? g_deg[i] : 0;
    s[t] = v;
    __syncthreads();
    #pragma unroll
    for (int off = 1; off < 1024; off <<= 1) {
        int u = (t >= off) ? s[t - off] : 0;
        __syncthreads();
        s[t] += u;
        __syncthreads();
    }
    if (i < N_NODES) {
        int ex = s[t] - v + g_boff[blockIdx.x];
        g_rowptr[i] = ex;
        g_cursor[i] = ex;
    }
}

__global__ void k_fill(const void* __restrict__ ei, const float* __restrict__ w) {
    int e = blockIdx.x * blockDim.x + threadIdx.x;
    if (e >= N_EDGES) return;
    int s, d;
    if (g_is64) {
        const long long* p = (const long long*)ei;
        s = (int)p[e]; d = (int)p[N_EDGES + e];
    } else {
        const int* p = (const int*)ei;
        s = p[e]; d = p[N_EDGES + e];
    }
    int pos = atomicAdd(&g_cursor[d], 1);
    if (g_wuni) {
        g_edge_raw[pos] = s;                          // src only, 4B
    } else {
        ((int2*)g_edge_raw)[pos] = make_int2(s, __float_as_int(w[e]));
    }
}

// ---------------- helpers ---------------------------------------------------
__device__ __forceinline__ void store_row_fp16(__half* base, int n, const float* o) {
    // 20 floats -> 10 half2 + 6 zero half2 -> 4 x 16B stores (full 64B row)
    unsigned hp[16];
    #pragma unroll
    for (int q = 0; q < 10; q++) {
        __half2 h = __floats2half2_rn(o[2 * q], o[2 * q + 1]);
        hp[q] = *(unsigned*)&h;
    }
    #pragma unroll
    for (int q = 10; q < 16; q++) hp[q] = 0u;
    uint4* op = (uint4*)(base + (size_t)n * ROWH);
    op[0] = make_uint4(hp[0], hp[1], hp[2], hp[3]);
    op[1] = make_uint4(hp[4], hp[5], hp[6], hp[7]);
    op[2] = make_uint4(hp[8], hp[9], hp[10], hp[11]);
    op[3] = make_uint4(hp[12], hp[13], hp[14], hp[15]);
}

// ---------------- layer-1 input GEMM: bufA = fp16(x @ W1a) ------------------
__global__ __launch_bounds__(256) void k_gemm_in(const float* __restrict__ x,
                                                 const float* __restrict__ W) {
    __shared__ float sW[F_IN * HID];   // 5.1 KB
    int tid = threadIdx.x;
    for (int i = tid; i < F_IN * HID; i += 256) sW[i] = W[i];
    __syncthreads();
    int n = blockIdx.x * 256 + tid;
    if (n >= N_NODES) return;

    const float4* xr = (const float4*)(x + (size_t)n * F_IN);

    float acc[HID];
    #pragma unroll
    for (int j = 0; j < HID; j++) acc[j] = 0.0f;

    #pragma unroll
    for (int c = 0; c < 4; c++) {
        float4 xv[4];
        #pragma unroll
        for (int q = 0; q < 4; q++) xv[q] = __ldg(xr + c * 4 + q);
        const float* xs = (const float*)xv;
        #pragma unroll
        for (int kk = 0; kk < 16; kk++) {
            int k = c * 16 + kk;
            float xk = xs[kk];
            const float4* wr = (const float4*)&sW[k * HID];
            #pragma unroll
            for (int q = 0; q < 5; q++) {
                float4 wv = wr[q];
                acc[4 * q + 0] += xk * wv.x;
                acc[4 * q + 1] += xk * wv.y;
                acc[4 * q + 2] += xk * wv.z;
                acc[4 * q + 3] += xk * wv.w;
            }
        }
    }
    store_row_fp16(g_bufA, n, acc);
}

// ---------------- aggregation: warp/node, 3-lane cooperative row gather -----
// 10 groups x 3 lanes per warp. Lane role r loads bytes [16r,16r+16) of the
// 64B-ALIGNED row: the 48B group access never crosses a 128B line -> exactly
// 1.0 wavefront/edge. Lean kernel (no MLP state) keeps occupancy high.
// mode selects input: 0,2 -> bufA ; 1 -> bufB.  Output: g_agg (fp32).
#define AW 8
__global__ __launch_bounds__(AW * 32) void k_agg(int mode) {
    __shared__ float red[AW][32][9];   // [warp][lane][8 feats + pad]
    int tid = threadIdx.x;
    int wid = tid >> 5, lane = tid & 31;
    int n = blockIdx.x * AW + wid;
    if (n >= N_NODES) return;

    const char* in = (const char*)((mode == 1) ? g_bufB : g_bufA);
    bool uni = (g_wuni != 0);
    int rs = __ldg(&g_rowptr[n]);
    int re = __ldg(&g_rowptr[n + 1]);

    int grp  = lane / 3;           // 0..9 valid; 10 for lanes 30,31
    int role = lane - grp * 3;     // 0..2
    bool active = grp < 10;

    float acc[8];
    #pragma unroll
    for (int j = 0; j < 8; j++) acc[j] = 0.0f;

    if (active) {
        if (uni) {
            const int* ep = g_edge_raw;
            for (int e = rs + grp; e < re; e += 10) {
                int s = __ldg(ep + e);                       // broadcast within group
                uint4 v = __ldg((const uint4*)(in + (size_t)s * 64) + role);
                unsigned hp[4] = {v.x, v.y, v.z, v.w};
                #pragma unroll
                for (int q = 0; q < 4; q++) {
                    float2 f = __half22float2(*(__half2*)&hp[q]);
                    acc[2 * q + 0] += f.x;
                    acc[2 * q + 1] += f.y;
                }
            }
        } else {
            const int2* ep = (const int2*)g_edge_raw;
            for (int e = rs + grp; e < re; e += 10) {
                int2 p = __ldg(ep + e);
                float w = __int_as_float(p.y);
                uint4 v = __ldg((const uint4*)(in + (size_t)p.x * 64) + role);
                unsigned hp[4] = {v.x, v.y, v.z, v.w};
                #pragma unroll
                for (int q = 0; q < 4; q++) {
                    float2 f = __half22float2(*(__half2*)&hp[q]);
                    acc[2 * q + 0] += f.x * w;
                    acc[2 * q + 1] += f.y * w;
                }
            }
        }
    }

    // reduction: feature f = 8*role + j lives in lanes {3g + role}, g = 0..9
    float (*rp)[9] = red[wid];
    #pragma unroll
    for (int j = 0; j < 8; j++) rp[lane][j] = acc[j];
    __syncwarp();

    if (lane < HID) {
        int r = lane >> 3, j = lane & 7;   // feature -> (role, slot)
        float s = 0.0f;
        #pragma unroll
        for (int g = 0; g < 10; g++) s += rp[3 * g + r][j];
        g_agg[(size_t)n * HID + lane] = s;               // coalesced 80B per warp
    }
}

// ---------------- node MLP; mode 2 fuses global pooling ---------------------
// mode: 0 -> bufB(fp16), 1 -> bufA(fp16), 2 -> pooled atomics (no row output)
__global__ __launch_bounds__(128) void k_mlp(const float* __restrict__ ba,
                                             const float* __restrict__ Wb,
                                             const float* __restrict__ bb,
                                             const float* __restrict__ Wn,
                                             const void* __restrict__ batch_v,
                                             int mode) {
    __shared__ float sWb[HID * HID], sWn[HID * HID], sba[HID], sbb[HID];
    int tid = threadIdx.x;
    for (int i = tid; i < HID * HID; i += 128) {
        sWb[i] = Wb[i];
        sWn[i] = Wn ? Wn[i] : 0.0f;
    }
    if (tid < HID) { sba[tid] = ba[tid]; sbb[tid] = bb[tid]; }
    __syncthreads();
    int n = blockIdx.x * 128 + tid;
    bool valid = n < N_NODES;
    if (!valid && mode != 2) return;

    float z[HID];
    if (valid) {
        float4 t[5];
        const float4* ag = (const float4*)(g_agg + (size_t)n * HID);
        #pragma unroll
        for (int i = 0; i < 5; i++) t[i] = __ldg(ag + i);
        float* zt = (float*)t;

        #pragma unroll
        for (int k = 0; k < HID; k++) z[k] = fmaxf(zt[k] + sba[k], 0.0f);

        float z2[HID];
        #pragma unroll
        for (int j = 0; j < HID; j++) {
            float a = sbb[j];
            #pragma unroll
            for (int k = 0; k < HID; k++) a += z[k] * sWb[k * HID + j];
            z2[j] = fmaxf(a, 0.0f);
        }

        float ss = 0.0f;
        #pragma unroll
        for (int k = 0; k < HID; k++) ss += z2[k] * z2[k];
        float inv = 1.0f / fmaxf(sqrtf(ss), EPS_NORM);
        #pragma unroll
        for (int k = 0; k < HID; k++) z[k] = fmaxf(z2[k] * inv, 0.0f);  // h
    } else {
        #pragma unroll
        for (int k = 0; k < HID; k++) z[k] = 0.0f;
    }

    if (mode != 2) {
        float o[HID];
        #pragma unroll
        for (int j = 0; j < HID; j++) {
            float a = 0.0f;
            #pragma unroll
            for (int k = 0; k < HID; k++) a += z[k] * sWn[k * HID + j];
            o[j] = a;
        }
        store_row_fp16((mode == 0) ? g_bufB : g_bufA, n, o);
        return;
    }

    // ---- fused global max/mean pooling (batch is sorted by graph) ----
    int g = -1;
    if (valid) {
        if (g_is64) g = (int)((const long long*)batch_v)[n];
        else        g = ((const int*)batch_v)[n];
    }
    const unsigned m = 0xffffffffu;
    int g0 = __shfl_sync(m, g, 0);
    bool uni = __all_sync(m, g == g0) && (g0 >= 0);
    int lane = tid & 31;

    if (uni) {
        #pragma unroll
        for (int f = 0; f < HID; f++) {
            float s = z[f], mx = z[f];
            #pragma unroll
            for (int off = 16; off > 0; off >>= 1) {
                s += __shfl_xor_sync(m, s, off);
                mx = fmaxf(mx, __shfl_xor_sync(m, mx, off));
            }
            if (lane == 0) {
                atomicAdd(&g_psum[g0 * HID + f], s);
                atomicMax((int*)&g_pmax[g0 * HID + f], __float_as_int(mx));  // h >= 0
            }
        }
        if (lane == 0) atomicAdd(&g_cnt[g0], 32.0f);
    } else if (valid) {
        #pragma unroll
        for (int f = 0; f < HID; f++) {
            atomicAdd(&g_psum[g * HID + f], z[f]);
            atomicMax((int*)&g_pmax[g * HID + f], __float_as_int(z[f]));
        }
        atomicAdd(&g_cnt[g], 1.0f);
    }
}

__global__ void k_final(const float* __restrict__ Wlin, const float* __restrict__ blin,
                        float* __restrict__ out) {
    int idx = blockIdx.x * blockDim.x + threadIdx.x;
    if (idx >= N_GRAPHS * N_CLASSES) return;
    int gph = idx / N_CLASSES, c = idx % N_CLASSES;
    float cnt = g_cnt[gph];
    float icnt = 1.0f / fmaxf(cnt, 1.0f);
    float acc = __ldg(blin + c);
    #pragma unroll
    for (int k = 0; k < HID; k++) {
        float mx = (cnt > 0.0f) ? g_pmax[gph * HID + k] : 0.0f;
        float mean = g_psum[gph * HID + k] * icnt;
        acc += mx * __ldg(Wlin + k * N_CLASSES + c)
             + mean * __ldg(Wlin + (HID + k) * N_CLASSES + c);
    }
    out[idx] = acc;
}

// ---------------- launch ----------------------------------------------------
extern "C" void kernel_launch(void* const* d_in, const int* in_sizes, int n_in,
                              void* d_out, int out_size) {
    const float* x    = (const float*)d_in[0];
    const void*  ei   = d_in[1];
    const void*  batch= d_in[2];
    const float* ew   = (const float*)d_in[3];
    const float* W1a  = (const float*)d_in[4];
    const float* b1a  = (const float*)d_in[5];
    const float* W1b  = (const float*)d_in[6];
    const float* b1b  = (const float*)d_in[7];
    const float* W2a  = (const float*)d_in[8];
    const float* b2a  = (const float*)d_in[9];
    const float* W2b  = (const float*)d_in[10];
    const float* b2b  = (const float*)d_in[11];
    const float* W3a  = (const float*)d_in[12];
    const float* b3a  = (const float*)d_in[13];
    const float* W3b  = (const float*)d_in[14];
    const float* b3b  = (const float*)d_in[15];
    const float* Wlin = (const float*)d_in[16];
    const float* blin = (const float*)d_in[17];
    float* out = (float*)d_out;

    const int eg = (N_EDGES + 255) / 256;
    const int ng = (N_NODES + 255) / 256;
    const int ag = (N_NODES + AW - 1) / AW;
    const int mg = (N_NODES + 127) / 128;
    const int gg = (N_NODES + 255) / 256;

    k_init<<<ng, 256>>>(ei);
    k_hist<<<eg, 256>>>(ei, ew);
    k_gemm_in<<<gg, 256>>>(x, W1a);
    k_scan1<<<SCAN_B, 1024>>>();
    k_scan2<<<1, 32>>>();
    k_scan3<<<SCAN_B, 1024>>>();
    k_fill<<<eg, 256>>>(ei, ew);

    // three layers: lean agg (1.0 wf/edge) + node MLP; layer 3 fuses pooling
    k_agg<<<ag, AW * 32>>>(0);  k_mlp<<<mg, 128>>>(b1a, W1b, b1b, W2a, nullptr, 0);
    k_agg<<<ag, AW * 32>>>(1);  k_mlp<<<mg, 128>>>(b2a, W2b, b2b, W3a, nullptr, 1);
    k_agg<<<ag, AW * 32>>>(2);  k_mlp<<<mg, 128>>>(b3a, W3b, b3b, nullptr, batch, 2);

    k_final<<<2, 640>>>(Wlin, blin, out);
}